// round 15
// baseline (speedup 1.0000x reference)
#include <cuda_runtime.h>
#include <cuda_bf16.h>
#include <cstdint>

#define NNODES 50000
#define DIM 256
#define NEDGE 400000
#define HEADS 8
#define DHEAD 32
#define CONCATD 1280
#define NCLS 7
#define EPSBN 1e-9f

static inline int cdiv(int a, int b) { return (a + b - 1) / b; }

// ---------------- scratch (device globals; no allocations allowed) ----------
__device__ float g_gat_fself[NNODES * DIM];
__device__ float g_gat_fneigh[NNODES * DIM];
__device__ float g_gcn_h[3][NNODES * DIM];
__device__ float g_self_h[NNODES * DIM];
__device__ float g_agg[4][NNODES * DIM];  // branch 0=GAT, 1..3=GCN (contiguous)
__device__ float g_atts[NNODES * HEADS];
__device__ float g_attn[NNODES * HEADS];
__device__ float g_concat[NNODES * CONCATD];
__device__ float g_stats5[5][2 * DIM];
__device__ float g_wpack[2 * 2 * DIM * DIM];
__device__ __nv_bfloat16 g_fin_hi[NNODES * DIM];
__device__ __nv_bfloat16 g_fin_lo[NNODES * DIM];
__device__ __nv_bfloat16 g_act_hi[4][NNODES * DIM];
__device__ __nv_bfloat16 g_act_lo[4][NNODES * DIM];
__device__ __nv_bfloat16 g_wt_hi[11 * DIM * DIM];
__device__ __nv_bfloat16 g_wt_lo[11 * DIM * DIM];

// ---------------- param structs (by-value; device pointers only) ------------
struct GemmBatch {
    const __nv_bfloat16* Ah[6];
    const __nv_bfloat16* Al[6];
    const __nv_bfloat16* Bh[6];
    const __nv_bfloat16* Bl[6];
    const float* bias[6];
    float* C[6];
    int relu[6];
};
struct WsplitBatch {
    const float* src[11];
};
struct EdgeBatch {
    const int* row[4];
    const int* col[4];
    const float* vals[4];
    const float* src[4];
    float* out[4];
};
struct BnStatsBatch {
    const float* x[5];
    float* stats[5];
    int relu[5];
};
struct BnNormBatch {
    const float* x[5];
    const float* stats[5];
    int relu[5];
    int tobf16[5];  // 1: write dh/dl ; 0: write float dst (stride CONCATD)
    __nv_bfloat16* dh[5];
    __nv_bfloat16* dl[5];
    float* dst[5];
};

// ---------------- utility ----------------
__global__ void zero_kernel(float* p, size_t n4) {
    size_t i = (blockIdx.x * (size_t)blockDim.x + threadIdx.x);
    if (i < n4) reinterpret_cast<float4*>(p)[i] = make_float4(0.f, 0.f, 0.f, 0.f);
}

__global__ void repack_kernel(const float* __restrict__ Ws, const float* __restrict__ Wn) {
    int idx = blockIdx.x * blockDim.x + threadIdx.x;
    if (idx >= 2 * HEADS * DIM * DHEAD) return;
    int l = idx / (HEADS * DIM * DHEAD);
    int rem = idx % (HEADS * DIM * DHEAD);
    int h = rem / (DIM * DHEAD);
    int d = (rem / DHEAD) % DIM;
    int k = rem % DHEAD;
    int dst = l * (2 * DIM * DIM) + d * DIM + h * DHEAD + k;
    g_wpack[dst] = Ws[idx];
    g_wpack[dst + DIM * DIM] = Wn[idx];
}

// Batched transpose+split: 11 weights in one launch (z = widx)
__global__ void wsplit_batch_kernel(WsplitBatch wb, __nv_bfloat16* __restrict__ dh,
                                    __nv_bfloat16* __restrict__ dl) {
    int z = blockIdx.y;
    int idx = blockIdx.x * blockDim.x + threadIdx.x;
    if (idx >= DIM * DIM) return;
    int n = idx >> 8, k = idx & 255;
    float v = wb.src[z][k * DIM + n];
    __nv_bfloat16 hi = __float2bfloat16(v);
    size_t o = (size_t)z * DIM * DIM + idx;
    dh[o] = hi;
    dl[o] = __float2bfloat16(v - __bfloat162float(hi));
}

__global__ void fsplit_kernel(const float* __restrict__ src, __nv_bfloat16* __restrict__ dh,
                              __nv_bfloat16* __restrict__ dl) {
    size_t idx = blockIdx.x * (size_t)blockDim.x + threadIdx.x;
    if (idx >= (size_t)NNODES * DIM) return;
    float v = src[idx];
    __nv_bfloat16 hi = __float2bfloat16(v);
    dh[idx] = hi;
    dl[idx] = __float2bfloat16(v - __bfloat162float(hi));
}

// ---------------- batched mma.sync bf16-split GEMM --------------------------
#define BK 64
#define ASTR 72

__device__ __forceinline__ void mma16816(float* c, const uint32_t* a, const uint32_t* b) {
    asm volatile(
        "mma.sync.aligned.m16n8k16.row.col.f32.bf16.bf16.f32 "
        "{%0,%1,%2,%3}, {%4,%5,%6,%7}, {%8,%9}, {%0,%1,%2,%3};"
        : "+f"(c[0]), "+f"(c[1]), "+f"(c[2]), "+f"(c[3])
        : "r"(a[0]), "r"(a[1]), "r"(a[2]), "r"(a[3]), "r"(b[0]), "r"(b[1]));
}

__global__ __launch_bounds__(256, 2) void gemm_mma_batch_kernel(GemmBatch gb, int M) {
    extern __shared__ __nv_bfloat16 sm[];
    __nv_bfloat16* sAh = sm;
    __nv_bfloat16* sAl = sm + 128 * ASTR;
    __nv_bfloat16* sBh = sm + 2 * 128 * ASTR;
    __nv_bfloat16* sBl = sm + 3 * 128 * ASTR;

    int z = blockIdx.z;
    const __nv_bfloat16* __restrict__ Ah = gb.Ah[z];
    const __nv_bfloat16* __restrict__ Al = gb.Al[z];
    const __nv_bfloat16* __restrict__ Bh = gb.Bh[z];
    const __nv_bfloat16* __restrict__ Bl = gb.Bl[z];
    const float* __restrict__ bias = gb.bias[z];
    float* __restrict__ C = gb.C[z];
    bool relu = gb.relu[z] != 0;

    int tid = threadIdx.x;
    int wid = tid >> 5, lane = tid & 31;
    int m0 = blockIdx.x * 128;
    int n0 = blockIdx.y * 128;
    int wm = (wid >> 2) * 64;
    int wn = (wid & 3) * 32;
    int lg = lane >> 2;
    int lt = lane & 3;

    float acc[4][4][4] = {};

    for (int k0 = 0; k0 < DIM; k0 += BK) {
        for (int i = tid; i < 1024; i += 256) {
            int r = i >> 3;
            int c8 = (i & 7) * 8;
            int soff = r * ASTR + c8;
            int m = m0 + r;
            uint4 vh = make_uint4(0, 0, 0, 0), vl = make_uint4(0, 0, 0, 0);
            if (m < M) {
                vh = *reinterpret_cast<const uint4*>(Ah + (size_t)m * DIM + k0 + c8);
                vl = *reinterpret_cast<const uint4*>(Al + (size_t)m * DIM + k0 + c8);
            }
            *reinterpret_cast<uint4*>(sAh + soff) = vh;
            *reinterpret_cast<uint4*>(sAl + soff) = vl;
            *reinterpret_cast<uint4*>(sBh + soff) =
                *reinterpret_cast<const uint4*>(Bh + (size_t)(n0 + r) * DIM + k0 + c8);
            *reinterpret_cast<uint4*>(sBl + soff) =
                *reinterpret_cast<const uint4*>(Bl + (size_t)(n0 + r) * DIM + k0 + c8);
        }
        __syncthreads();

#pragma unroll
        for (int kk = 0; kk < BK; kk += 16) {
            uint32_t bh[4][2], bl[4][2];
#pragma unroll
            for (int nt = 0; nt < 4; ++nt) {
                int n = wn + nt * 8 + lg;
                int k = kk + lt * 2;
                bh[nt][0] = *reinterpret_cast<uint32_t*>(sBh + n * ASTR + k);
                bh[nt][1] = *reinterpret_cast<uint32_t*>(sBh + n * ASTR + k + 8);
                bl[nt][0] = *reinterpret_cast<uint32_t*>(sBl + n * ASTR + k);
                bl[nt][1] = *reinterpret_cast<uint32_t*>(sBl + n * ASTR + k + 8);
            }
#pragma unroll
            for (int mt = 0; mt < 4; ++mt) {
                int r = wm + mt * 16 + lg;
                int k = kk + lt * 2;
                uint32_t ah[4], al[4];
                ah[0] = *reinterpret_cast<uint32_t*>(sAh + r * ASTR + k);
                ah[1] = *reinterpret_cast<uint32_t*>(sAh + (r + 8) * ASTR + k);
                ah[2] = *reinterpret_cast<uint32_t*>(sAh + r * ASTR + k + 8);
                ah[3] = *reinterpret_cast<uint32_t*>(sAh + (r + 8) * ASTR + k + 8);
                al[0] = *reinterpret_cast<uint32_t*>(sAl + r * ASTR + k);
                al[1] = *reinterpret_cast<uint32_t*>(sAl + (r + 8) * ASTR + k);
                al[2] = *reinterpret_cast<uint32_t*>(sAl + r * ASTR + k + 8);
                al[3] = *reinterpret_cast<uint32_t*>(sAl + (r + 8) * ASTR + k + 8);
#pragma unroll
                for (int nt = 0; nt < 4; ++nt) {
                    mma16816(acc[mt][nt], ah, bh[nt]);
                    mma16816(acc[mt][nt], ah, bl[nt]);
                    mma16816(acc[mt][nt], al, bh[nt]);
                }
            }
        }
        __syncthreads();
    }

#pragma unroll
    for (int mt = 0; mt < 4; ++mt) {
        int r = m0 + wm + mt * 16 + lg;
#pragma unroll
        for (int nt = 0; nt < 4; ++nt) {
            int col = n0 + wn + nt * 8 + lt * 2;
            float2 bv = *reinterpret_cast<const float2*>(bias + col);
            if (r < M) {
                float2 v;
                v.x = acc[mt][nt][0] + bv.x;
                v.y = acc[mt][nt][1] + bv.y;
                if (relu) {
                    v.x = fmaxf(v.x, 0.f);
                    v.y = fmaxf(v.y, 0.f);
                }
                *reinterpret_cast<float2*>(C + (size_t)r * DIM + col) = v;
            }
            if (r + 8 < M) {
                float2 v;
                v.x = acc[mt][nt][2] + bv.x;
                v.y = acc[mt][nt][3] + bv.y;
                if (relu) {
                    v.x = fmaxf(v.x, 0.f);
                    v.y = fmaxf(v.y, 0.f);
                }
                *reinterpret_cast<float2*>(C + (size_t)(r + 8) * DIM + col) = v;
            }
        }
    }
}

#define SMEM_MMA (4 * 128 * ASTR * 2)

// ---------------- GAT attention logits ----------------
__global__ __launch_bounds__(256) void att_kernel(const float* __restrict__ fself,
                                                  const float* __restrict__ a_s,
                                                  const float* __restrict__ a_n,
                                                  float* __restrict__ att_s,
                                                  float* __restrict__ att_n) {
    __shared__ float sf[32 * 257];
    __shared__ float sa_s[256], sa_n[256];
    int tid = threadIdx.x;
    int n0 = blockIdx.x * 32;
    int nvalid = min(32, NNODES - n0);
    sa_s[tid] = a_s[tid];
    sa_n[tid] = a_n[tid];
    for (int i = tid; i < nvalid * 256; i += 256) {
        int node = i >> 8, j = i & 255;
        sf[node * 257 + j] = fself[(size_t)(n0 + node) * 256 + j];
    }
    __syncthreads();
    int h = tid >> 5, node = tid & 31;
    if (node < nvalid) {
        const float* f = &sf[node * 257 + h * 32];
        float ss = 0.f, sn = 0.f;
#pragma unroll
        for (int k = 0; k < 32; ++k) {
            float v = f[k];
            ss += v * sa_s[h * 32 + k];
            sn += v * sa_n[h * 32 + k];
        }
        int o = (n0 + node) * 8 + h;
        att_s[o] = ss < 0.f ? 0.2f * ss : ss;
        att_n[o] = sn < 0.f ? 0.2f * sn : sn;
    }
}

// ---------------- fused edge aggregation (all graphs, one launch) -----------
__device__ __forceinline__ void red_add_v4(float* p, float x, float y, float z, float w) {
    asm volatile("red.global.add.v4.f32 [%0], {%1,%2,%3,%4};" ::"l"(p), "f"(x), "f"(y), "f"(z),
                 "f"(w)
                 : "memory");
}

// grid: (cdiv(E,4), ngraphs); block (64,4). g==0 -> GAT (uses att), else GCN.
__global__ void edge_batch_kernel(EdgeBatch eb, const float* __restrict__ att_s,
                                  const float* __restrict__ att_n, int hasGat) {
    int g = blockIdx.y;
    int e = blockIdx.x * 4 + threadIdx.y;
    if (e >= NEDGE) return;
    const int* __restrict__ row = eb.row[g];
    const int* __restrict__ col = eb.col[g];
    int r = row[e], c = col[e];
    int t = threadIdx.x;
    float coef = eb.vals[g][e];
    if (hasGat && g == 0) {
        int h = t >> 3;
        coef *= (att_s[r * 8 + h] + att_n[c * 8 + h]);
    }
    float4 fn = *reinterpret_cast<const float4*>(eb.src[g] + (size_t)c * 256 + t * 4);
    red_add_v4(eb.out[g] + (size_t)r * 256 + t * 4, coef * fn.x, coef * fn.y, coef * fn.z,
               coef * fn.w);
}

// ---------------- fused BatchNorm ----------------
__global__ void bn_stats_batch_kernel(BnStatsBatch bb) {
    int z = blockIdx.y;
    const float* __restrict__ x = bb.x[z];
    bool relu = bb.relu[z] != 0;
    int col = threadIdx.x;
    int r0 = blockIdx.x * 256;
    int rend = min(r0 + 256, NNODES);
    float s = 0.f, s2 = 0.f;
    for (int r = r0; r < rend; ++r) {
        float v = x[(size_t)r * 256 + col];
        if (relu) v = fmaxf(v, 0.f);
        s += v;
        s2 += v * v;
    }
    atomicAdd(&bb.stats[z][col], s);
    atomicAdd(&bb.stats[z][256 + col], s2);
}

__global__ void bn_norm_batch_kernel(BnNormBatch nb) {
    int z = blockIdx.y;
    size_t idx = blockIdx.x * (size_t)blockDim.x + threadIdx.x;
    if (idx >= (size_t)NNODES * 256) return;
    const float* __restrict__ stats = nb.stats[z];
    int col = (int)(idx & 255);
    size_t rowi = idx >> 8;
    const float invM = 1.f / NNODES;
    float mean = stats[col] * invM;
    float var = stats[256 + col] * invM - mean * mean;
    float istd = rsqrtf(var + EPSBN);
    float v = nb.x[z][idx];
    if (nb.relu[z]) v = fmaxf(v, 0.f);
    float nv = (v - mean) * istd;
    if (nb.tobf16[z]) {
        __nv_bfloat16 hi = __float2bfloat16(nv);
        nb.dh[z][idx] = hi;
        nb.dl[z][idx] = __float2bfloat16(nv - __bfloat162float(hi));
    } else {
        nb.dst[z][rowi * CONCATD + col] = nv;
    }
}

// ---------------- classifier ----------------
__global__ void cls_kernel(const float* __restrict__ feat, const float* __restrict__ W,
                           const float* __restrict__ b, float* __restrict__ out) {
    __shared__ float sW[CONCATD * NCLS];
    for (int i = threadIdx.x; i < CONCATD * NCLS; i += blockDim.x) sW[i] = W[i];
    __syncthreads();
    int warp = threadIdx.x >> 5, lane = threadIdx.x & 31;
    int n = blockIdx.x * (blockDim.x >> 5) + warp;
    if (n >= NNODES) return;
    float acc[NCLS] = {};
    const float* f = feat + (size_t)n * CONCATD;
    for (int j = lane; j < CONCATD; j += 32) {
        float v = f[j];
#pragma unroll
        for (int c = 0; c < NCLS; ++c) acc[c] += v * sW[j * NCLS + c];
    }
#pragma unroll
    for (int c = 0; c < NCLS; ++c)
        for (int off = 16; off; off >>= 1) acc[c] += __shfl_down_sync(0xffffffffu, acc[c], off);
    if (lane == 0) {
#pragma unroll
        for (int c = 0; c < NCLS; ++c) out[(size_t)n * NCLS + c] = acc[c] + b[c];
    }
}

// ---------------- host orchestration (single stream, batched phases) --------
extern "C" void kernel_launch(void* const* d_in, const int* in_sizes, int n_in,
                              void* d_out, int out_size) {
    const float* f_in = (const float*)d_in[0];
    const int* erows = (const int*)d_in[1];
    const int* ecols = (const int*)d_in[2];
    const float* evals = (const float*)d_in[3];
    const float* gat_Ws = (const float*)d_in[4];
    const float* gat_bs = (const float*)d_in[5];
    const float* gat_Wn = (const float*)d_in[6];
    const float* gat_bn = (const float*)d_in[7];
    const float* gat_as = (const float*)d_in[8];
    const float* gat_an = (const float*)d_in[9];
    const float* gcn_W = (const float*)d_in[10];
    const float* gcn_b = (const float*)d_in[11];
    const float* self_W = (const float*)d_in[12];
    const float* self_b = (const float*)d_in[13];
    const float* cls_W = (const float*)d_in[14];
    const float* cls_b = (const float*)d_in[15];
    float* out = (float*)d_out;

    float *gat_fself, *gat_fneigh, *gcn_h, *self_h, *agg, *atts, *attn, *cc, *stats5, *wpack;
    __nv_bfloat16 *finh, *finl, *acth, *actl, *wth, *wtl;
    cudaGetSymbolAddress((void**)&gat_fself, g_gat_fself);
    cudaGetSymbolAddress((void**)&gat_fneigh, g_gat_fneigh);
    cudaGetSymbolAddress((void**)&gcn_h, g_gcn_h);
    cudaGetSymbolAddress((void**)&self_h, g_self_h);
    cudaGetSymbolAddress((void**)&agg, g_agg);
    cudaGetSymbolAddress((void**)&atts, g_atts);
    cudaGetSymbolAddress((void**)&attn, g_attn);
    cudaGetSymbolAddress((void**)&cc, g_concat);
    cudaGetSymbolAddress((void**)&stats5, g_stats5);
    cudaGetSymbolAddress((void**)&wpack, g_wpack);
    cudaGetSymbolAddress((void**)&finh, g_fin_hi);
    cudaGetSymbolAddress((void**)&finl, g_fin_lo);
    cudaGetSymbolAddress((void**)&acth, g_act_hi);
    cudaGetSymbolAddress((void**)&actl, g_act_lo);
    cudaGetSymbolAddress((void**)&wth, g_wt_hi);
    cudaGetSymbolAddress((void**)&wtl, g_wt_lo);

    cudaFuncSetAttribute(gemm_mma_batch_kernel, cudaFuncAttributeMaxDynamicSharedMemorySize,
                         SMEM_MMA);

    const int feat4 = NNODES * DIM / 4;
    const int normBlocks = cdiv(NNODES * DIM, 256);
    const dim3 eblock(64, 4);
    const int egrid = cdiv(NEDGE, 4);
    const int wblocks = cdiv(DIM * DIM, 256);
    const size_t WSZ = (size_t)DIM * DIM;
    const size_t FSZ = (size_t)NNODES * DIM;

    // ===== phase 0: weight/feature prep =====
    repack_kernel<<<cdiv(2 * HEADS * DIM * DHEAD, 256), 256>>>(gat_Ws, gat_Wn);
    {
        WsplitBatch wb;
        for (int i = 0; i < 4; ++i) wb.src[i] = wpack + i * WSZ;
        for (int i = 0; i < 6; ++i) wb.src[4 + i] = gcn_W + i * WSZ;
        wb.src[10] = self_W;
        wsplit_batch_kernel<<<dim3(wblocks, 11), 256>>>(wb, wth, wtl);
    }
    fsplit_kernel<<<normBlocks, 256>>>(f_in, finh, finl);
    zero_kernel<<<cdiv(4 * feat4 + 640, 256), 256>>>(agg, 4 * feat4);  // agg
    zero_kernel<<<3, 256>>>(stats5, 5 * 128);                          // stats (2560 floats)

    // ===== phase 1: layer-0 batched GEMM (6 GEMMs, all A = f_in) =====
    {
        GemmBatch gb;
        float* outs[6] = {gat_fself, gat_fneigh, gcn_h, gcn_h + FSZ, gcn_h + 2 * FSZ, self_h};
        int widx[6] = {0, 1, 4, 6, 8, 10};
        const float* biases[6] = {gat_bs, gat_bn, gcn_b, gcn_b + 2 * DIM, gcn_b + 4 * DIM, self_b};
        int relu[6] = {1, 1, 0, 0, 0, 1};
        for (int z = 0; z < 6; ++z) {
            gb.Ah[z] = finh;
            gb.Al[z] = finl;
            gb.Bh[z] = wth + (size_t)widx[z] * WSZ;
            gb.Bl[z] = wtl + (size_t)widx[z] * WSZ;
            gb.bias[z] = biases[z];
            gb.C[z] = outs[z];
            gb.relu[z] = relu[z];
        }
        gemm_mma_batch_kernel<<<dim3(cdiv(NNODES, 128), 2, 6), 256, SMEM_MMA>>>(gb, NNODES);
    }
    att_kernel<<<cdiv(NNODES, 32), 256>>>(gat_fself, gat_as, gat_an, atts, attn);

    // ===== phase 2: fused edge scatter (4 graphs) =====
    EdgeBatch eb;
    for (int g = 0; g < 4; ++g) {
        eb.row[g] = erows + (size_t)g * NEDGE;
        eb.col[g] = ecols + (size_t)g * NEDGE;
        eb.vals[g] = evals + (size_t)g * NEDGE;
        eb.out[g] = agg + (size_t)g * FSZ;
    }
    eb.src[0] = gat_fneigh;
    eb.src[1] = gcn_h;
    eb.src[2] = gcn_h + FSZ;
    eb.src[3] = gcn_h + 2 * FSZ;
    edge_batch_kernel<<<dim3(egrid, 4), eblock>>>(eb, atts, attn, 1);

    // ===== phase 3: fused BN stats+norm (5 branches: 4 agg + self_h) =====
    {
        BnStatsBatch bb;
        for (int z = 0; z < 4; ++z) {
            bb.x[z] = agg + (size_t)z * FSZ;
            bb.stats[z] = stats5 + z * 512;
            bb.relu[z] = (z == 0) ? 0 : 1;
        }
        bb.x[4] = self_h;
        bb.stats[4] = stats5 + 4 * 512;
        bb.relu[4] = 0;
        bn_stats_batch_kernel<<<dim3(cdiv(NNODES, 256), 5), 256>>>(bb);

        BnNormBatch nb;
        for (int z = 0; z < 4; ++z) {
            nb.x[z] = agg + (size_t)z * FSZ;
            nb.stats[z] = stats5 + z * 512;
            nb.relu[z] = (z == 0) ? 0 : 1;
            nb.tobf16[z] = 1;
            nb.dh[z] = acth + (size_t)z * FSZ;
            nb.dl[z] = actl + (size_t)z * FSZ;
            nb.dst[z] = nullptr;
        }
        nb.x[4] = self_h;
        nb.stats[4] = stats5 + 4 * 512;
        nb.relu[4] = 0;
        nb.tobf16[4] = 0;
        nb.dh[4] = nullptr;
        nb.dl[4] = nullptr;
        nb.dst[4] = cc + 4 * 256;
        bn_norm_batch_kernel<<<dim3(normBlocks, 5), 256>>>(nb);
    }

    // ===== phase 4: layer-1 batched GEMM (5 GEMMs) =====
    zero_kernel<<<cdiv(4 * feat4 + 640, 256), 256>>>(agg, 4 * feat4);
    zero_kernel<<<3, 256>>>(stats5, 5 * 128);
    {
        GemmBatch gb;
        const __nv_bfloat16* ah[5] = {acth, acth, acth + FSZ, acth + 2 * FSZ, acth + 3 * FSZ};
        const __nv_bfloat16* al[5] = {actl, actl, actl + FSZ, actl + 2 * FSZ, actl + 3 * FSZ};
        float* outs[5] = {gat_fself, gat_fneigh, gcn_h, gcn_h + FSZ, gcn_h + 2 * FSZ};
        int widx[5] = {2, 3, 5, 7, 9};
        const float* biases[5] = {gat_bs + 256, gat_bn + 256, gcn_b + DIM, gcn_b + 3 * DIM,
                                  gcn_b + 5 * DIM};
        int relu[5] = {1, 1, 0, 0, 0};
        for (int z = 0; z < 5; ++z) {
            gb.Ah[z] = ah[z];
            gb.Al[z] = al[z];
            gb.Bh[z] = wth + (size_t)widx[z] * WSZ;
            gb.Bl[z] = wtl + (size_t)widx[z] * WSZ;
            gb.bias[z] = biases[z];
            gb.C[z] = outs[z];
            gb.relu[z] = relu[z];
        }
        gb.Ah[5] = gb.Al[5] = gb.Bh[5] = gb.Bl[5] = nullptr;
        gb.bias[5] = nullptr;
        gb.C[5] = nullptr;
        gb.relu[5] = 0;
        gemm_mma_batch_kernel<<<dim3(cdiv(NNODES, 128), 2, 5), 256, SMEM_MMA>>>(gb, NNODES);
    }
    att_kernel<<<cdiv(NNODES, 32), 256>>>(gat_fself, gat_as + 256, gat_an + 256, atts, attn);

    // ===== phase 5: fused edge scatter layer 1 =====
    edge_batch_kernel<<<dim3(egrid, 4), eblock>>>(eb, atts, attn, 1);

    // ===== phase 6: fused BN stats+norm into concat =====
    {
        BnStatsBatch bb;
        for (int z = 0; z < 4; ++z) {
            bb.x[z] = agg + (size_t)z * FSZ;
            bb.stats[z] = stats5 + z * 512;
            bb.relu[z] = (z == 0) ? 0 : 1;
        }
        bb.x[4] = agg;  // unused slot (grid y only 4)
        bb.stats[4] = stats5 + 4 * 512;
        bb.relu[4] = 0;
        bn_stats_batch_kernel<<<dim3(cdiv(NNODES, 256), 4), 256>>>(bb);

        BnNormBatch nb;
        for (int z = 0; z < 4; ++z) {
            nb.x[z] = agg + (size_t)z * FSZ;
            nb.stats[z] = stats5 + z * 512;
            nb.relu[z] = (z == 0) ? 0 : 1;
            nb.tobf16[z] = 0;
            nb.dh[z] = nullptr;
            nb.dl[z] = nullptr;
            nb.dst[z] = cc + z * 256;
        }
        nb.x[4] = agg;
        nb.stats[4] = stats5 + 4 * 512;
        nb.relu[4] = 0;
        nb.tobf16[4] = 0;
        nb.dh[4] = nb.dl[4] = nullptr;
        nb.dst[4] = cc;
        bn_norm_batch_kernel<<<dim3(normBlocks, 4), 256>>>(nb);
    }

    // ===== classifier =====
    cls_kernel<<<cdiv(NNODES, 8), 256>>>(cc, cls_W, cls_b, out);
}

// round 16
// speedup vs baseline: 1.3071x; 1.3071x over previous
#include <cuda_runtime.h>
#include <cuda_bf16.h>
#include <cstdint>

#define NNODES 50000
#define DIM 256
#define NEDGE 400000
#define HEADS 8
#define DHEAD 32
#define CONCATD 1280
#define NCLS 7
#define EPSBN 1e-9f

static inline int cdiv(int a, int b) { return (a + b - 1) / b; }

// ---------------- scratch (device globals; no allocations allowed) ----------
__device__ float g_buf0[NNODES * DIM];   // GEMM out / f_self
__device__ float g_buf1[NNODES * DIM];   // agg out
__device__ float g_buf2[NNODES * DIM];   // f_neigh
__device__ float g_atts[NNODES * HEADS];
__device__ float g_attn[NNODES * HEADS];
__device__ float g_concat[NNODES * CONCATD];
__device__ float g_stats[2 * DIM];
__device__ float g_wpack[2 * 2 * DIM * DIM];
__device__ __nv_bfloat16 g_fin_hi[NNODES * DIM];
__device__ __nv_bfloat16 g_fin_lo[NNODES * DIM];
__device__ __nv_bfloat16 g_act_hi[NNODES * DIM];
__device__ __nv_bfloat16 g_act_lo[NNODES * DIM];
__device__ __nv_bfloat16 g_wt_hi[11 * DIM * DIM];
__device__ __nv_bfloat16 g_wt_lo[11 * DIM * DIM];
// CSR structures (4 graphs)
__device__ int g_cnt[4 * NNODES];
__device__ int g_rowptr[4 * (NNODES + 1)];
__device__ int g_fill[4 * NNODES];
__device__ int g_ecol[4 * NEDGE];
__device__ float g_eval[4 * NEDGE];

struct WsplitBatch {
    const float* src[11];
};

// ---------------- utility ----------------
__global__ void zero_kernel(float* p, size_t n4) {
    size_t i = (blockIdx.x * (size_t)blockDim.x + threadIdx.x);
    if (i < n4) reinterpret_cast<float4*>(p)[i] = make_float4(0.f, 0.f, 0.f, 0.f);
}

__global__ void repack_kernel(const float* __restrict__ Ws, const float* __restrict__ Wn) {
    int idx = blockIdx.x * blockDim.x + threadIdx.x;
    if (idx >= 2 * HEADS * DIM * DHEAD) return;
    int l = idx / (HEADS * DIM * DHEAD);
    int rem = idx % (HEADS * DIM * DHEAD);
    int h = rem / (DIM * DHEAD);
    int d = (rem / DHEAD) % DIM;
    int k = rem % DHEAD;
    int dst = l * (2 * DIM * DIM) + d * DIM + h * DHEAD + k;
    g_wpack[dst] = Ws[idx];
    g_wpack[dst + DIM * DIM] = Wn[idx];
}

__global__ void wsplit_batch_kernel(WsplitBatch wb, __nv_bfloat16* __restrict__ dh,
                                    __nv_bfloat16* __restrict__ dl) {
    int z = blockIdx.y;
    int idx = blockIdx.x * blockDim.x + threadIdx.x;
    if (idx >= DIM * DIM) return;
    int n = idx >> 8, k = idx & 255;
    float v = wb.src[z][k * DIM + n];
    __nv_bfloat16 hi = __float2bfloat16(v);
    size_t o = (size_t)z * DIM * DIM + idx;
    dh[o] = hi;
    dl[o] = __float2bfloat16(v - __bfloat162float(hi));
}

__global__ void fsplit_kernel(const float* __restrict__ src, __nv_bfloat16* __restrict__ dh,
                              __nv_bfloat16* __restrict__ dl) {
    size_t idx = blockIdx.x * (size_t)blockDim.x + threadIdx.x;
    if (idx >= (size_t)NNODES * DIM) return;
    float v = src[idx];
    __nv_bfloat16 hi = __float2bfloat16(v);
    dh[idx] = hi;
    dl[idx] = __float2bfloat16(v - __bfloat162float(hi));
}

// ---------------- CSR build ----------------
__global__ void hist_kernel(const int* __restrict__ rows, int* __restrict__ cnt) {
    int g = blockIdx.y;
    int e = blockIdx.x * blockDim.x + threadIdx.x;
    if (e >= NEDGE) return;
    atomicAdd(&cnt[(size_t)g * NNODES + rows[(size_t)g * NEDGE + e]], 1);
}

__global__ __launch_bounds__(1024) void scan_kernel(const int* __restrict__ cnt,
                                                    int* __restrict__ rowptr,
                                                    int* __restrict__ fill) {
    int g = blockIdx.x;
    const int* c = cnt + (size_t)g * NNODES;
    int* rp = rowptr + (size_t)g * (NNODES + 1);
    int* fl = fill + (size_t)g * NNODES;
    __shared__ int sh[1024];
    int t = threadIdx.x;
    const int CH = 49;  // 1024*49 >= 50000
    int start = t * CH;
    int end = min(start + CH, NNODES);
    int s = 0;
    for (int i = start; i < end; ++i) s += c[i];
    sh[t] = s;
    __syncthreads();
    // Hillis-Steele inclusive scan
    for (int d = 1; d < 1024; d <<= 1) {
        int v = (t >= d) ? sh[t - d] : 0;
        __syncthreads();
        sh[t] += v;
        __syncthreads();
    }
    int run = (t == 0) ? 0 : sh[t - 1];
    for (int i = start; i < end; ++i) {
        rp[i] = run;
        fl[i] = run;
        run += c[i];
    }
    if (t == 0) rp[NNODES] = sh[1023];
}

__global__ void scatter_kernel(const int* __restrict__ rows, const int* __restrict__ cols,
                               const float* __restrict__ vals, int* __restrict__ fill,
                               int* __restrict__ ecol, float* __restrict__ eval) {
    int g = blockIdx.y;
    int e = blockIdx.x * blockDim.x + threadIdx.x;
    if (e >= NEDGE) return;
    int r = rows[(size_t)g * NEDGE + e];
    int pos = atomicAdd(&fill[(size_t)g * NNODES + r], 1);
    ecol[(size_t)g * NEDGE + pos] = cols[(size_t)g * NEDGE + e];
    eval[(size_t)g * NEDGE + pos] = vals[(size_t)g * NEDGE + e];
}

// ---------------- mma.sync bf16-split GEMM (R12-proven) ---------------------
#define BK 64
#define ASTR 72

__device__ __forceinline__ void mma16816(float* c, const uint32_t* a, const uint32_t* b) {
    asm volatile(
        "mma.sync.aligned.m16n8k16.row.col.f32.bf16.bf16.f32 "
        "{%0,%1,%2,%3}, {%4,%5,%6,%7}, {%8,%9}, {%0,%1,%2,%3};"
        : "+f"(c[0]), "+f"(c[1]), "+f"(c[2]), "+f"(c[3])
        : "r"(a[0]), "r"(a[1]), "r"(a[2]), "r"(a[3]), "r"(b[0]), "r"(b[1]));
}

template <bool RELU>
__global__ __launch_bounds__(256, 2) void gemm_mma_kernel(
    const __nv_bfloat16* __restrict__ Ah, const __nv_bfloat16* __restrict__ Al,
    const __nv_bfloat16* __restrict__ Bh, const __nv_bfloat16* __restrict__ Bl,
    const float* __restrict__ bias, float* __restrict__ C, int M) {
    extern __shared__ __nv_bfloat16 sm[];
    __nv_bfloat16* sAh = sm;
    __nv_bfloat16* sAl = sm + 128 * ASTR;
    __nv_bfloat16* sBh = sm + 2 * 128 * ASTR;
    __nv_bfloat16* sBl = sm + 3 * 128 * ASTR;

    int tid = threadIdx.x;
    int wid = tid >> 5, lane = tid & 31;
    int m0 = blockIdx.x * 128;
    int n0 = blockIdx.y * 128;
    int wm = (wid >> 2) * 64;
    int wn = (wid & 3) * 32;
    int lg = lane >> 2;
    int lt = lane & 3;

    float acc[4][4][4] = {};

    for (int k0 = 0; k0 < DIM; k0 += BK) {
        for (int i = tid; i < 1024; i += 256) {
            int r = i >> 3;
            int c8 = (i & 7) * 8;
            int soff = r * ASTR + c8;
            int m = m0 + r;
            uint4 vh = make_uint4(0, 0, 0, 0), vl = make_uint4(0, 0, 0, 0);
            if (m < M) {
                vh = *reinterpret_cast<const uint4*>(Ah + (size_t)m * DIM + k0 + c8);
                vl = *reinterpret_cast<const uint4*>(Al + (size_t)m * DIM + k0 + c8);
            }
            *reinterpret_cast<uint4*>(sAh + soff) = vh;
            *reinterpret_cast<uint4*>(sAl + soff) = vl;
            *reinterpret_cast<uint4*>(sBh + soff) =
                *reinterpret_cast<const uint4*>(Bh + (size_t)(n0 + r) * DIM + k0 + c8);
            *reinterpret_cast<uint4*>(sBl + soff) =
                *reinterpret_cast<const uint4*>(Bl + (size_t)(n0 + r) * DIM + k0 + c8);
        }
        __syncthreads();

#pragma unroll
        for (int kk = 0; kk < BK; kk += 16) {
            uint32_t bh[4][2], bl[4][2];
#pragma unroll
            for (int nt = 0; nt < 4; ++nt) {
                int n = wn + nt * 8 + lg;
                int k = kk + lt * 2;
                bh[nt][0] = *reinterpret_cast<uint32_t*>(sBh + n * ASTR + k);
                bh[nt][1] = *reinterpret_cast<uint32_t*>(sBh + n * ASTR + k + 8);
                bl[nt][0] = *reinterpret_cast<uint32_t*>(sBl + n * ASTR + k);
                bl[nt][1] = *reinterpret_cast<uint32_t*>(sBl + n * ASTR + k + 8);
            }
#pragma unroll
            for (int mt = 0; mt < 4; ++mt) {
                int r = wm + mt * 16 + lg;
                int k = kk + lt * 2;
                uint32_t ah[4], al[4];
                ah[0] = *reinterpret_cast<uint32_t*>(sAh + r * ASTR + k);
                ah[1] = *reinterpret_cast<uint32_t*>(sAh + (r + 8) * ASTR + k);
                ah[2] = *reinterpret_cast<uint32_t*>(sAh + r * ASTR + k + 8);
                ah[3] = *reinterpret_cast<uint32_t*>(sAh + (r + 8) * ASTR + k + 8);
                al[0] = *reinterpret_cast<uint32_t*>(sAl + r * ASTR + k);
                al[1] = *reinterpret_cast<uint32_t*>(sAl + (r + 8) * ASTR + k);
                al[2] = *reinterpret_cast<uint32_t*>(sAl + r * ASTR + k + 8);
                al[3] = *reinterpret_cast<uint32_t*>(sAl + (r + 8) * ASTR + k + 8);
#pragma unroll
                for (int nt = 0; nt < 4; ++nt) {
                    mma16816(acc[mt][nt], ah, bh[nt]);
                    mma16816(acc[mt][nt], ah, bl[nt]);
                    mma16816(acc[mt][nt], al, bh[nt]);
                }
            }
        }
        __syncthreads();
    }

#pragma unroll
    for (int mt = 0; mt < 4; ++mt) {
        int r = m0 + wm + mt * 16 + lg;
#pragma unroll
        for (int nt = 0; nt < 4; ++nt) {
            int col = n0 + wn + nt * 8 + lt * 2;
            float2 bv = *reinterpret_cast<const float2*>(bias + col);
            if (r < M) {
                float2 v;
                v.x = acc[mt][nt][0] + bv.x;
                v.y = acc[mt][nt][1] + bv.y;
                if (RELU) {
                    v.x = fmaxf(v.x, 0.f);
                    v.y = fmaxf(v.y, 0.f);
                }
                *reinterpret_cast<float2*>(C + (size_t)r * DIM + col) = v;
            }
            if (r + 8 < M) {
                float2 v;
                v.x = acc[mt][nt][2] + bv.x;
                v.y = acc[mt][nt][3] + bv.y;
                if (RELU) {
                    v.x = fmaxf(v.x, 0.f);
                    v.y = fmaxf(v.y, 0.f);
                }
                *reinterpret_cast<float2*>(C + (size_t)(r + 8) * DIM + col) = v;
            }
        }
    }
}

#define SMEM_MMA (4 * 128 * ASTR * 2)

// ---------------- GAT attention logits ----------------
__global__ __launch_bounds__(256) void att_kernel(const float* __restrict__ fself,
                                                  const float* __restrict__ a_s,
                                                  const float* __restrict__ a_n,
                                                  float* __restrict__ att_s,
                                                  float* __restrict__ att_n) {
    __shared__ float sf[32 * 257];
    __shared__ float sa_s[256], sa_n[256];
    int tid = threadIdx.x;
    int n0 = blockIdx.x * 32;
    int nvalid = min(32, NNODES - n0);
    sa_s[tid] = a_s[tid];
    sa_n[tid] = a_n[tid];
    for (int i = tid; i < nvalid * 256; i += 256) {
        int node = i >> 8, j = i & 255;
        sf[node * 257 + j] = fself[(size_t)(n0 + node) * 256 + j];
    }
    __syncthreads();
    int h = tid >> 5, node = tid & 31;
    if (node < nvalid) {
        const float* f = &sf[node * 257 + h * 32];
        float ss = 0.f, sn = 0.f;
#pragma unroll
        for (int k = 0; k < 32; ++k) {
            float v = f[k];
            ss += v * sa_s[h * 32 + k];
            sn += v * sa_n[h * 32 + k];
        }
        int o = (n0 + node) * 8 + h;
        att_s[o] = ss < 0.f ? 0.2f * ss : ss;
        att_n[o] = sn < 0.f ? 0.2f * sn : sn;
    }
}

// ---------------- CSR segmented aggregation (warp per row) ------------------
__global__ __launch_bounds__(256) void gcn_csr_kernel(const int* __restrict__ rowptr,
                                                      const int* __restrict__ ecol,
                                                      const float* __restrict__ eval,
                                                      const float* __restrict__ h,
                                                      float* __restrict__ out) {
    int w = blockIdx.x * 8 + (threadIdx.x >> 5);
    if (w >= NNODES) return;
    int lane = threadIdx.x & 31;
    int beg = rowptr[w], end = rowptr[w + 1];
    float4 a0 = make_float4(0.f, 0.f, 0.f, 0.f), a1 = a0;
    for (int i = beg; i < end; ++i) {
        int c = ecol[i];
        float v = eval[i];
        const float4* fp = reinterpret_cast<const float4*>(h + (size_t)c * 256);
        float4 f0 = fp[lane];
        float4 f1 = fp[32 + lane];
        a0.x += v * f0.x; a0.y += v * f0.y; a0.z += v * f0.z; a0.w += v * f0.w;
        a1.x += v * f1.x; a1.y += v * f1.y; a1.z += v * f1.z; a1.w += v * f1.w;
    }
    float4* op = reinterpret_cast<float4*>(out + (size_t)w * 256);
    op[lane] = a0;
    op[32 + lane] = a1;
}

__global__ __launch_bounds__(256) void gat_csr_kernel(
    const int* __restrict__ rowptr, const int* __restrict__ ecol,
    const float* __restrict__ eval, const float* __restrict__ att_s,
    const float* __restrict__ att_n, const float* __restrict__ h, float* __restrict__ out) {
    int w = blockIdx.x * 8 + (threadIdx.x >> 5);
    if (w >= NNODES) return;
    int lane = threadIdx.x & 31;
    int h0 = lane >> 3, h1 = 4 + (lane >> 3);
    float as0 = att_s[w * 8 + h0];
    float as1 = att_s[w * 8 + h1];
    int beg = rowptr[w], end = rowptr[w + 1];
    float4 a0 = make_float4(0.f, 0.f, 0.f, 0.f), a1 = a0;
    for (int i = beg; i < end; ++i) {
        int c = ecol[i];
        float v = eval[i];
        float c0 = (as0 + att_n[c * 8 + h0]) * v;
        float c1 = (as1 + att_n[c * 8 + h1]) * v;
        const float4* fp = reinterpret_cast<const float4*>(h + (size_t)c * 256);
        float4 f0 = fp[lane];
        float4 f1 = fp[32 + lane];
        a0.x += c0 * f0.x; a0.y += c0 * f0.y; a0.z += c0 * f0.z; a0.w += c0 * f0.w;
        a1.x += c1 * f1.x; a1.y += c1 * f1.y; a1.z += c1 * f1.z; a1.w += c1 * f1.w;
    }
    float4* op = reinterpret_cast<float4*>(out + (size_t)w * 256);
    op[lane] = a0;
    op[32 + lane] = a1;
}

// ---------------- BatchNorm ----------------
template <bool RELU>
__global__ void bn_stats_kernel(const float* __restrict__ x, float* __restrict__ stats) {
    int col = threadIdx.x;
    int r0 = blockIdx.x * 256;
    int rend = min(r0 + 256, NNODES);
    float s = 0.f, s2 = 0.f;
    for (int r = r0; r < rend; ++r) {
        float v = x[(size_t)r * 256 + col];
        if (RELU) v = fmaxf(v, 0.f);
        s += v;
        s2 += v * v;
    }
    atomicAdd(&stats[col], s);
    atomicAdd(&stats[256 + col], s2);
}

template <bool RELU>
__global__ void bn_norm_kernel(const float* __restrict__ x, const float* __restrict__ stats,
                               float* __restrict__ dst, int dstStride) {
    size_t idx = blockIdx.x * (size_t)blockDim.x + threadIdx.x;
    if (idx >= (size_t)NNODES * 256) return;
    int col = (int)(idx & 255);
    size_t rowi = idx >> 8;
    const float invM = 1.f / NNODES;
    float mean = stats[col] * invM;
    float var = stats[256 + col] * invM - mean * mean;
    float istd = rsqrtf(var + EPSBN);
    float v = x[idx];
    if (RELU) v = fmaxf(v, 0.f);
    dst[rowi * dstStride + col] = (v - mean) * istd;
}

template <bool RELU>
__global__ void bn_norm_bf16_kernel(const float* __restrict__ x, const float* __restrict__ stats,
                                    __nv_bfloat16* __restrict__ dh,
                                    __nv_bfloat16* __restrict__ dl) {
    size_t idx = blockIdx.x * (size_t)blockDim.x + threadIdx.x;
    if (idx >= (size_t)NNODES * 256) return;
    int col = (int)(idx & 255);
    const float invM = 1.f / NNODES;
    float mean = stats[col] * invM;
    float var = stats[256 + col] * invM - mean * mean;
    float istd = rsqrtf(var + EPSBN);
    float v = x[idx];
    if (RELU) v = fmaxf(v, 0.f);
    float nv = (v - mean) * istd;
    __nv_bfloat16 hi = __float2bfloat16(nv);
    dh[idx] = hi;
    dl[idx] = __float2bfloat16(nv - __bfloat162float(hi));
}

// ---------------- classifier ----------------
__global__ void cls_kernel(const float* __restrict__ feat, const float* __restrict__ W,
                           const float* __restrict__ b, float* __restrict__ out) {
    __shared__ float sW[CONCATD * NCLS];
    for (int i = threadIdx.x; i < CONCATD * NCLS; i += blockDim.x) sW[i] = W[i];
    __syncthreads();
    int warp = threadIdx.x >> 5, lane = threadIdx.x & 31;
    int n = blockIdx.x * (blockDim.x >> 5) + warp;
    if (n >= NNODES) return;
    float acc[NCLS] = {};
    const float* f = feat + (size_t)n * CONCATD;
    for (int j = lane; j < CONCATD; j += 32) {
        float v = f[j];
#pragma unroll
        for (int c = 0; c < NCLS; ++c) acc[c] += v * sW[j * NCLS + c];
    }
#pragma unroll
    for (int c = 0; c < NCLS; ++c)
        for (int off = 16; off; off >>= 1) acc[c] += __shfl_down_sync(0xffffffffu, acc[c], off);
    if (lane == 0) {
#pragma unroll
        for (int c = 0; c < NCLS; ++c) out[(size_t)n * NCLS + c] = acc[c] + b[c];
    }
}

// ---------------- host orchestration ----------------
extern "C" void kernel_launch(void* const* d_in, const int* in_sizes, int n_in,
                              void* d_out, int out_size) {
    const float* f_in = (const float*)d_in[0];
    const int* erows = (const int*)d_in[1];
    const int* ecols = (const int*)d_in[2];
    const float* evals = (const float*)d_in[3];
    const float* gat_Ws = (const float*)d_in[4];
    const float* gat_bs = (const float*)d_in[5];
    const float* gat_Wn = (const float*)d_in[6];
    const float* gat_bn = (const float*)d_in[7];
    const float* gat_as = (const float*)d_in[8];
    const float* gat_an = (const float*)d_in[9];
    const float* gcn_W = (const float*)d_in[10];
    const float* gcn_b = (const float*)d_in[11];
    const float* self_W = (const float*)d_in[12];
    const float* self_b = (const float*)d_in[13];
    const float* cls_W = (const float*)d_in[14];
    const float* cls_b = (const float*)d_in[15];
    float* out = (float*)d_out;

    float *buf0, *buf1, *buf2, *atts, *attn, *cc, *stats, *wpack, *evalb;
    int *cnt, *rowptr, *fill, *ecolb;
    __nv_bfloat16 *finh, *finl, *acth, *actl, *wth, *wtl;
    cudaGetSymbolAddress((void**)&buf0, g_buf0);
    cudaGetSymbolAddress((void**)&buf1, g_buf1);
    cudaGetSymbolAddress((void**)&buf2, g_buf2);
    cudaGetSymbolAddress((void**)&atts, g_atts);
    cudaGetSymbolAddress((void**)&attn, g_attn);
    cudaGetSymbolAddress((void**)&cc, g_concat);
    cudaGetSymbolAddress((void**)&stats, g_stats);
    cudaGetSymbolAddress((void**)&wpack, g_wpack);
    cudaGetSymbolAddress((void**)&finh, g_fin_hi);
    cudaGetSymbolAddress((void**)&finl, g_fin_lo);
    cudaGetSymbolAddress((void**)&acth, g_act_hi);
    cudaGetSymbolAddress((void**)&actl, g_act_lo);
    cudaGetSymbolAddress((void**)&wth, g_wt_hi);
    cudaGetSymbolAddress((void**)&wtl, g_wt_lo);
    cudaGetSymbolAddress((void**)&cnt, g_cnt);
    cudaGetSymbolAddress((void**)&rowptr, g_rowptr);
    cudaGetSymbolAddress((void**)&fill, g_fill);
    cudaGetSymbolAddress((void**)&ecolb, g_ecol);
    cudaGetSymbolAddress((void**)&evalb, g_eval);

    cudaFuncSetAttribute(gemm_mma_kernel<true>, cudaFuncAttributeMaxDynamicSharedMemorySize,
                         SMEM_MMA);
    cudaFuncSetAttribute(gemm_mma_kernel<false>, cudaFuncAttributeMaxDynamicSharedMemorySize,
                         SMEM_MMA);

    const dim3 mgrid(cdiv(NNODES, 128), 2);
    const int normBlocks = cdiv(NNODES * DIM, 256);
    const int csrBlocks = cdiv(NNODES, 8);
    const int eBlocks = cdiv(NEDGE, 256);
    const int wblocks = cdiv(DIM * DIM, 256);
    const size_t WSZ = (size_t)DIM * DIM;

    // ===== prep: weights, feature split, CSR build =====
    repack_kernel<<<cdiv(2 * HEADS * DIM * DHEAD, 256), 256>>>(gat_Ws, gat_Wn);
    {
        WsplitBatch wb;
        for (int i = 0; i < 4; ++i) wb.src[i] = wpack + i * WSZ;
        for (int i = 0; i < 6; ++i) wb.src[4 + i] = gcn_W + i * WSZ;
        wb.src[10] = self_W;
        wsplit_batch_kernel<<<dim3(wblocks, 11), 256>>>(wb, wth, wtl);
    }
    fsplit_kernel<<<normBlocks, 256>>>(f_in, finh, finl);
    zero_kernel<<<cdiv(NNODES, 256), 256>>>((float*)cnt, NNODES);  // 4*NNODES ints
    hist_kernel<<<dim3(eBlocks, 4), 256>>>(erows, cnt);
    scan_kernel<<<4, 1024>>>(cnt, rowptr, fill);
    scatter_kernel<<<dim3(eBlocks, 4), 256>>>(erows, ecols, evals, fill, ecolb, evalb);

    // ===== GAT branch (graph 0) =====
    {
        const int* rp = rowptr;
        const int* ec = ecolb;
        const float* ev = evalb;
        const __nv_bfloat16 *fh = finh, *fl = finl;
        for (int l = 0; l < 2; ++l) {
            const __nv_bfloat16* Wsh = wth + (size_t)(l * 2) * WSZ;
            const __nv_bfloat16* Wsl = wtl + (size_t)(l * 2) * WSZ;
            const __nv_bfloat16* Wnh = wth + (size_t)(l * 2 + 1) * WSZ;
            const __nv_bfloat16* Wnl = wtl + (size_t)(l * 2 + 1) * WSZ;
            gemm_mma_kernel<true><<<mgrid, 256, SMEM_MMA>>>(fh, fl, Wsh, Wsl, gat_bs + l * 256,
                                                            buf0, NNODES);
            gemm_mma_kernel<true><<<mgrid, 256, SMEM_MMA>>>(fh, fl, Wnh, Wnl, gat_bn + l * 256,
                                                            buf2, NNODES);
            att_kernel<<<cdiv(NNODES, 32), 256>>>(buf0, gat_as + l * 256, gat_an + l * 256, atts,
                                                  attn);
            gat_csr_kernel<<<csrBlocks, 256>>>(rp, ec, ev, atts, attn, buf2, buf1);
            zero_kernel<<<1, 128>>>(stats, 128);
            bn_stats_kernel<false><<<cdiv(NNODES, 256), 256>>>(buf1, stats);
            if (l == 0) {
                bn_norm_bf16_kernel<false><<<normBlocks, 256>>>(buf1, stats, acth, actl);
                fh = acth;
                fl = actl;
            } else {
                bn_norm_kernel<false><<<normBlocks, 256>>>(buf1, stats, cc + 0, CONCATD);
            }
        }
    }

    // ===== 3 vanilla GCN branches (graphs 1..3) =====
    for (int g = 0; g < 3; ++g) {
        const int* rp = rowptr + (size_t)(g + 1) * (NNODES + 1);
        const int* ec = ecolb + (size_t)(g + 1) * NEDGE;
        const float* ev = evalb + (size_t)(g + 1) * NEDGE;
        const __nv_bfloat16 *fh = finh, *fl = finl;
        for (int l = 0; l < 2; ++l) {
            int widx = 4 + g * 2 + l;
            const float* b = gcn_b + (size_t)(g * 2 + l) * DIM;
            gemm_mma_kernel<false><<<mgrid, 256, SMEM_MMA>>>(
                fh, fl, wth + (size_t)widx * WSZ, wtl + (size_t)widx * WSZ, b, buf0, NNODES);
            gcn_csr_kernel<<<csrBlocks, 256>>>(rp, ec, ev, buf0, buf1);
            zero_kernel<<<1, 128>>>(stats, 128);
            bn_stats_kernel<true><<<cdiv(NNODES, 256), 256>>>(buf1, stats);
            if (l == 0) {
                bn_norm_bf16_kernel<true><<<normBlocks, 256>>>(buf1, stats, acth, actl);
                fh = acth;
                fl = actl;
            } else {
                bn_norm_kernel<true><<<normBlocks, 256>>>(buf1, stats, cc + (1 + g) * 256,
                                                          CONCATD);
            }
        }
    }

    // ===== self perceptron branch =====
    gemm_mma_kernel<true><<<mgrid, 256, SMEM_MMA>>>(finh, finl, wth + 10 * WSZ, wtl + 10 * WSZ,
                                                    self_b, buf0, NNODES);
    zero_kernel<<<1, 128>>>(stats, 128);
    bn_stats_kernel<false><<<cdiv(NNODES, 256), 256>>>(buf0, stats);
    bn_norm_kernel<false><<<normBlocks, 256>>>(buf0, stats, cc + 4 * 256, CONCATD);

    // ===== classifier =====
    cls_kernel<<<cdiv(NNODES, 8), 256>>>(cc, cls_W, cls_b, out);
}